// round 1
// baseline (speedup 1.0000x reference)
#include <cuda_runtime.h>
#include <math.h>
#include <stdint.h>

// ---------------- problem constants ----------------
#define BB    16
#define NP1   65
#define NT    (BB*NP1)      // 1040 tokens
#define MM    256
#define DD    512
#define NH    8
#define DH    64
#define LL    3
#define DFFN  2048
#define U_SIZE (NT*MM)      // 266240 floats (u_pot)

// ---------------- scratch (static device allocations) ----------------
__device__ float g_xs  [NT*DD];      // residual stream
__device__ float g_qkv [NT*3*DD];    // qkv buffer, reused for proj / ff2 outputs
__device__ float g_attn[NT*DD];      // attention output
__device__ float g_ff  [NT*DFFN];    // ff1 output
__device__ float g_hraw[NT*MM];      // h head output

// ---------------- helpers ----------------
__device__ __forceinline__ float gelu_exact(float x) {
    return 0.5f * x * (1.0f + erff(x * 0.70710678118654752440f));
}

// block-wide sum, 256 threads
__device__ __forceinline__ float blockSum256(float v, float* sm) {
    int tid = threadIdx.x;
    #pragma unroll
    for (int o = 16; o > 0; o >>= 1) v += __shfl_down_sync(0xffffffffu, v, o);
    if ((tid & 31) == 0) sm[tid >> 5] = v;
    __syncthreads();
    if (tid < 8) {
        v = sm[tid];
        #pragma unroll
        for (int o = 4; o > 0; o >>= 1) v += __shfl_down_sync(0xffu, v, o);
        if (tid == 0) sm[0] = v;
    }
    __syncthreads();
    float r = sm[0];
    __syncthreads();
    return r;
}

// ---------------- embed: conv+mean (analytic) -> fc -> LN -> gelu -> +pos ----------------
__global__ void embed_kernel(const float* __restrict__ marg,
                             const float* __restrict__ conv_w,
                             const float* __restrict__ conv_b,
                             const float* __restrict__ fc_w,
                             const float* __restrict__ fc_b,
                             const float* __restrict__ ln_g,
                             const float* __restrict__ ln_b,
                             const float* __restrict__ pos) {
    int t   = blockIdx.x;          // token 0..1039
    int tid = threadIdx.x;         // 256 threads
    __shared__ float red[8];
    __shared__ float e128[128];

    const float* x = marg + (size_t)t * MM;
    float S = blockSum256(x[tid], red);

    if (tid < 128) {
        float x0 = x[0], x1 = x[1], x254 = x[254], x255 = x[255];
        float T0 = S - x254 - x255;
        float T1 = S - x255;
        float T2 = S;
        float T3 = S - x0;
        float T4 = S - x0 - x1;
        const float* w = conv_w + tid * 5;
        e128[tid] = conv_b[tid] +
            (w[0]*T0 + w[1]*T1 + w[2]*T2 + w[3]*T3 + w[4]*T4) * (1.0f/256.0f);
    }
    __syncthreads();

    // fc: 128 -> 512 (each thread owns cols tid and tid+256)
    float y0 = fc_b[tid];
    float y1 = fc_b[tid + 256];
    #pragma unroll 8
    for (int k = 0; k < 128; k++) {
        float e = e128[k];
        y0 = fmaf(e, fc_w[k*DD + tid],       y0);
        y1 = fmaf(e, fc_w[k*DD + tid + 256], y1);
    }
    // layernorm over 512
    float s  = blockSum256(y0 + y1, red);
    float mu = s * (1.0f/512.0f);
    float d0 = y0 - mu, d1 = y1 - mu;
    float vs = blockSum256(d0*d0 + d1*d1, red);
    float inv = rsqrtf(vs * (1.0f/512.0f) + 1e-5f);

    int p = t % NP1;
    float z0 = gelu_exact(d0*inv*ln_g[tid]       + ln_b[tid])       + pos[p*DD + tid];
    float z1 = gelu_exact(d1*inv*ln_g[tid + 256] + ln_b[tid + 256]) + pos[p*DD + tid + 256];
    g_xs[(size_t)t*DD + tid]       = z0;
    g_xs[(size_t)t*DD + tid + 256] = z1;
}

// ---------------- generic SGEMM: C[M,N] = A[M,K] * W[N,K]^T + bias, optional gelu ----------------
// 64x64 tile, BK=16, 256 threads, 4x4 microtile.
template <int ACT>
__global__ void gemm_nt(const float* __restrict__ A,
                        const float* __restrict__ W,
                        const float* __restrict__ bias,
                        float* __restrict__ C,
                        int M, int N, int K) {
    __shared__ float As[16][68];   // [k][m], padded for 16B-aligned LDS.128
    __shared__ float Bs[16][68];   // [k][n]
    int bn = blockIdx.x * 64;
    int bm = blockIdx.y * 64;
    int tid = threadIdx.x;
    int tx = tid & 15;             // n-group
    int ty = tid >> 4;             // m-group

    float acc[4][4];
    #pragma unroll
    for (int i = 0; i < 4; i++)
        #pragma unroll
        for (int j = 0; j < 4; j++) acc[i][j] = 0.0f;

    for (int k0 = 0; k0 < K; k0 += 16) {
        #pragma unroll
        for (int i = 0; i < 4; i++) {
            int lin = tid + i*256;
            int r = lin >> 4, c = lin & 15;
            int gr = bm + r;
            As[c][r] = (gr < M) ? A[(size_t)gr*K + k0 + c] : 0.0f;
            Bs[c][r] = W[(size_t)(bn + r)*K + k0 + c];
        }
        __syncthreads();
        #pragma unroll
        for (int kk = 0; kk < 16; kk++) {
            float a[4], b[4];
            #pragma unroll
            for (int i = 0; i < 4; i++) a[i] = As[kk][ty*4 + i];
            #pragma unroll
            for (int j = 0; j < 4; j++) b[j] = Bs[kk][tx*4 + j];
            #pragma unroll
            for (int i = 0; i < 4; i++)
                #pragma unroll
                for (int j = 0; j < 4; j++) acc[i][j] = fmaf(a[i], b[j], acc[i][j]);
        }
        __syncthreads();
    }

    #pragma unroll
    for (int i = 0; i < 4; i++) {
        int row = bm + ty*4 + i;
        if (row >= M) continue;
        #pragma unroll
        for (int j = 0; j < 4; j++) {
            int col = bn + tx*4 + j;
            float v = acc[i][j] + bias[col];
            if (ACT == 1) v = gelu_exact(v);
            C[(size_t)row*N + col] = v;
        }
    }
}

// ---------------- attention: one block per (b, h) ----------------
__global__ void attn_kernel(const float* __restrict__ qkv, float* __restrict__ out) {
    int b = blockIdx.x, h = blockIdx.y;
    __shared__ float sk[NP1 * (DH + 1)];   // padded to kill bank conflicts
    __shared__ float ss[NP1 * NP1];        // 4225 scores
    int tid = threadIdx.x;                 // 256

    // load K into smem (padded rows)
    for (int idx = tid; idx < NP1*DH; idx += 256) {
        int t = idx >> 6, d = idx & 63;
        size_t base = (size_t)(b*NP1 + t) * (3*DD) + h*DH + d;
        sk[t*(DH+1) + d] = qkv[base + DD];
    }
    __syncthreads();

    // scores: q (global, broadcast within warp) dot k (smem)
    const float scale = 0.125f;  // 1/sqrt(64)
    for (int idx = tid; idx < NP1*NP1; idx += 256) {
        int r = idx / NP1, c = idx - r*NP1;
        const float* q = qkv + (size_t)(b*NP1 + r) * (3*DD) + h*DH;
        const float* kk = sk + c*(DH+1);
        float s = 0.0f;
        #pragma unroll 16
        for (int d = 0; d < DH; d++) s = fmaf(__ldg(q + d), kk[d], s);
        ss[idx] = s * scale;
    }
    __syncthreads();

    // softmax per row (65 rows, one thread each)
    if (tid < NP1) {
        float* row = ss + tid*NP1;
        float m = row[0];
        for (int j = 1; j < NP1; j++) m = fmaxf(m, row[j]);
        float sum = 0.0f;
        for (int j = 0; j < NP1; j++) { float e = __expf(row[j] - m); row[j] = e; sum += e; }
        float inv = 1.0f / sum;
        for (int j = 0; j < NP1; j++) row[j] *= inv;
    }
    __syncthreads();

    // O = att @ V  (V streamed from global, coalesced + L1-resident)
    for (int idx = tid; idx < NP1*DH; idx += 256) {
        int r = idx >> 6, d = idx & 63;
        const float* row = ss + r*NP1;
        float o = 0.0f;
        #pragma unroll 5
        for (int t = 0; t < NP1; t++) {
            const float* v = qkv + (size_t)(b*NP1 + t) * (3*DD) + 2*DD + h*DH + d;
            o = fmaf(row[t], __ldg(v), o);
        }
        out[(size_t)(b*NP1 + r)*DD + h*DH + d] = o;
    }
}

// ---------------- residual add + layernorm (in-place on xs) ----------------
__global__ void resid_ln_kernel(float* __restrict__ xs,
                                const float* __restrict__ add,
                                const float* __restrict__ g,
                                const float* __restrict__ bb) {
    int t = blockIdx.x, tid = threadIdx.x;   // 256 threads, 2 cols each
    __shared__ float red[8];
    size_t base = (size_t)t * DD;
    float v0 = xs[base + tid]       + add[base + tid];
    float v1 = xs[base + tid + 256] + add[base + tid + 256];
    float s  = blockSum256(v0 + v1, red);
    float mu = s * (1.0f/512.0f);
    float d0 = v0 - mu, d1 = v1 - mu;
    float vs = blockSum256(d0*d0 + d1*d1, red);
    float inv = rsqrtf(vs * (1.0f/512.0f) + 1e-5f);
    xs[base + tid]       = d0*inv*g[tid]       + bb[tid];
    xs[base + tid + 256] = d1*inv*g[tid + 256] + bb[tid + 256];
}

// ---------------- final drift / correction -> h_pot ----------------
// One block per (b, n<64); thread i computes the geometric softmax row i.
__global__ void hpot_kernel(const float* __restrict__ marg,
                            const float* __restrict__ xg,
                            float* __restrict__ out) {
    int b = blockIdx.x, n = blockIdx.y;
    int i = threadIdx.x;                    // 256
    __shared__ float sx[256];
    __shared__ float red[8];
    sx[i] = xg[i];
    __syncthreads();

    float hr = g_hraw[(size_t)(b*NP1 + n)*MM + i];
    float xi = sx[i];
    float c  = hr * 100.0f;                 // 1/EPS_PROJ
    // logits l_j = c*(xi - x_j): linear in j -> max at an endpoint
    float m = fmaxf(c*(xi - sx[0]), c*(xi - sx[255]));
    float s0 = 0.0f, s1 = 0.0f;
    #pragma unroll 8
    for (int j = 0; j < 256; j++) {
        float xj = sx[j];
        float e = __expf(fmaf(c, xi - xj, -m));
        s0 += e;
        s1 = fmaf(e, xj, s1);
    }
    float drift = s1 / s0 - xi;
    float mu = marg[(size_t)(b*NP1 + n)*MM + i];
    float wd = blockSum256(mu * drift, red);
    float wm = blockSum256(mu, red);
    float corr = wd / (wm + 1e-8f);
    out[U_SIZE + (size_t)(b*64 + n)*MM + i] = hr - corr;
}

// ---------------- launch ----------------
extern "C" void kernel_launch(void* const* d_in, const int* in_sizes, int n_in,
                              void* d_out, int out_size) {
    const float* marg   = (const float*)d_in[0];
    const float* xg     = (const float*)d_in[1];
    const float* conv_w = (const float*)d_in[2];
    const float* conv_b = (const float*)d_in[3];
    const float* fc_w   = (const float*)d_in[4];
    const float* fc_b   = (const float*)d_in[5];
    const float* ln0_g  = (const float*)d_in[6];
    const float* ln0_b  = (const float*)d_in[7];
    const float* pos    = (const float*)d_in[8];
    const float* qkv_w  = (const float*)d_in[9];
    const float* qkv_b  = (const float*)d_in[10];
    const float* out_w  = (const float*)d_in[11];
    const float* out_b  = (const float*)d_in[12];
    const float* ln1_g  = (const float*)d_in[13];
    const float* ln1_b  = (const float*)d_in[14];
    const float* ff1_w  = (const float*)d_in[15];
    const float* ff1_b  = (const float*)d_in[16];
    const float* ff2_w  = (const float*)d_in[17];
    const float* ff2_b  = (const float*)d_in[18];
    const float* ln2_g  = (const float*)d_in[19];
    const float* ln2_b  = (const float*)d_in[20];
    const float* u_w    = (const float*)d_in[21];
    const float* u_b    = (const float*)d_in[22];
    const float* h_w    = (const float*)d_in[23];
    const float* h_b    = (const float*)d_in[24];
    float* out = (float*)d_out;

    float *xs, *qkvb, *attnb, *ffb, *hraw;
    cudaGetSymbolAddress((void**)&xs,    g_xs);
    cudaGetSymbolAddress((void**)&qkvb,  g_qkv);
    cudaGetSymbolAddress((void**)&attnb, g_attn);
    cudaGetSymbolAddress((void**)&ffb,   g_ff);
    cudaGetSymbolAddress((void**)&hraw,  g_hraw);

    const int GM = (NT + 63) / 64;   // 17

    embed_kernel<<<NT, 256>>>(marg, conv_w, conv_b, fc_w, fc_b, ln0_g, ln0_b, pos);

    for (int l = 0; l < LL; l++) {
        // qkv projection
        gemm_nt<0><<<dim3((3*DD)/64, GM), 256>>>(
            xs, qkv_w + (size_t)l*3*DD*DD, qkv_b + (size_t)l*3*DD, qkvb, NT, 3*DD, DD);
        // attention
        attn_kernel<<<dim3(BB, NH), 256>>>(qkvb, attnb);
        // output projection (reuse qkv buffer)
        gemm_nt<0><<<dim3(DD/64, GM), 256>>>(
            attnb, out_w + (size_t)l*DD*DD, out_b + (size_t)l*DD, qkvb, NT, DD, DD);
        resid_ln_kernel<<<NT, 256>>>(xs, qkvb, ln1_g + (size_t)l*DD, ln1_b + (size_t)l*DD);
        // ff1 (+gelu)
        gemm_nt<1><<<dim3(DFFN/64, GM), 256>>>(
            xs, ff1_w + (size_t)l*DFFN*DD, ff1_b + (size_t)l*DFFN, ffb, NT, DFFN, DD);
        // ff2
        gemm_nt<0><<<dim3(DD/64, GM), 256>>>(
            ffb, ff2_w + (size_t)l*DD*DFFN, ff2_b + (size_t)l*DD, qkvb, NT, DD, DFFN);
        resid_ln_kernel<<<NT, 256>>>(xs, qkvb, ln2_g + (size_t)l*DD, ln2_b + (size_t)l*DD);
    }

    // heads: u_pot straight into out, h_raw into scratch
    gemm_nt<0><<<dim3(MM/64, GM), 256>>>(xs, u_w, u_b, out,  NT, MM, DD);
    gemm_nt<0><<<dim3(MM/64, GM), 256>>>(xs, h_w, h_b, hraw, NT, MM, DD);

    // drift + correction -> h_pot
    hpot_kernel<<<dim3(BB, 64), 256>>>(marg, xg, out);
}

// round 2
// speedup vs baseline: 1.7198x; 1.7198x over previous
#include <cuda_runtime.h>
#include <math.h>
#include <stdint.h>

// ---------------- problem constants ----------------
#define BB    16
#define NP1   65
#define NT    (BB*NP1)      // 1040 tokens
#define MM    256
#define DD    512
#define NH    8
#define DH    64
#define LL    3
#define DFFN  2048
#define U_SIZE (NT*MM)      // 266240 floats (u_pot)

// ---------------- scratch (static device allocations) ----------------
__device__ float g_xs  [NT*DD];      // residual stream
__device__ float g_qkv [NT*3*DD];    // qkv buffer, reused for proj / ff2 outputs
__device__ float g_attn[NT*DD];      // attention output
__device__ float g_ff  [NT*DFFN];    // ff1 output
__device__ float g_hraw[NT*MM];      // h head output

// ---------------- helpers ----------------
__device__ __forceinline__ float gelu_exact(float x) {
    return 0.5f * x * (1.0f + erff(x * 0.70710678118654752440f));
}

__device__ __forceinline__ float blockSum256(float v, float* sm) {
    int tid = threadIdx.x;
    #pragma unroll
    for (int o = 16; o > 0; o >>= 1) v += __shfl_down_sync(0xffffffffu, v, o);
    if ((tid & 31) == 0) sm[tid >> 5] = v;
    __syncthreads();
    if (tid < 8) {
        v = sm[tid];
        #pragma unroll
        for (int o = 4; o > 0; o >>= 1) v += __shfl_down_sync(0xffu, v, o);
        if (tid == 0) sm[0] = v;
    }
    __syncthreads();
    float r = sm[0];
    __syncthreads();
    return r;
}

// ---------------- tf32 split helpers ----------------
__device__ __forceinline__ uint32_t f2tf32(float x) {
    uint32_t r; asm("cvt.rna.tf32.f32 %0, %1;" : "=r"(r) : "f"(x)); return r;
}
__device__ __forceinline__ void split_tf32(float x, uint32_t& hi, uint32_t& lo) {
    hi = f2tf32(x);
    float r = x - __uint_as_float(hi);
    lo = f2tf32(r);
}
__device__ __forceinline__ void mma8(float* d, const uint32_t* a, const uint32_t* b) {
    asm volatile(
        "mma.sync.aligned.m16n8k8.row.col.f32.tf32.tf32.f32 "
        "{%0,%1,%2,%3}, {%4,%5,%6,%7}, {%8,%9}, {%0,%1,%2,%3};"
        : "+f"(d[0]), "+f"(d[1]), "+f"(d[2]), "+f"(d[3])
        : "r"(a[0]), "r"(a[1]), "r"(a[2]), "r"(a[3]), "r"(b[0]), "r"(b[1]));
}

// ---------------- embed: conv+mean (analytic) -> fc -> LN -> gelu -> +pos ----------------
__global__ void embed_kernel(const float* __restrict__ marg,
                             const float* __restrict__ conv_w,
                             const float* __restrict__ conv_b,
                             const float* __restrict__ fc_w,
                             const float* __restrict__ fc_b,
                             const float* __restrict__ ln_g,
                             const float* __restrict__ ln_b,
                             const float* __restrict__ pos) {
    int t   = blockIdx.x;
    int tid = threadIdx.x;
    __shared__ float red[8];
    __shared__ float e128[128];

    const float* x = marg + (size_t)t * MM;
    float S = blockSum256(x[tid], red);

    if (tid < 128) {
        float x0 = x[0], x1 = x[1], x254 = x[254], x255 = x[255];
        float T0 = S - x254 - x255;
        float T1 = S - x255;
        float T2 = S;
        float T3 = S - x0;
        float T4 = S - x0 - x1;
        const float* w = conv_w + tid * 5;
        e128[tid] = conv_b[tid] +
            (w[0]*T0 + w[1]*T1 + w[2]*T2 + w[3]*T3 + w[4]*T4) * (1.0f/256.0f);
    }
    __syncthreads();

    float y0 = fc_b[tid];
    float y1 = fc_b[tid + 256];
    #pragma unroll 8
    for (int k = 0; k < 128; k++) {
        float e = e128[k];
        y0 = fmaf(e, fc_w[k*DD + tid],       y0);
        y1 = fmaf(e, fc_w[k*DD + tid + 256], y1);
    }
    float s  = blockSum256(y0 + y1, red);
    float mu = s * (1.0f/512.0f);
    float d0 = y0 - mu, d1 = y1 - mu;
    float vs = blockSum256(d0*d0 + d1*d1, red);
    float inv = rsqrtf(vs * (1.0f/512.0f) + 1e-5f);

    int p = t % NP1;
    float z0 = gelu_exact(d0*inv*ln_g[tid]       + ln_b[tid])       + pos[p*DD + tid];
    float z1 = gelu_exact(d1*inv*ln_g[tid + 256] + ln_b[tid + 256]) + pos[p*DD + tid + 256];
    g_xs[(size_t)t*DD + tid]       = z0;
    g_xs[(size_t)t*DD + tid + 256] = z1;
}

// ---------------- 3xTF32 tensor-core GEMM ----------------
// C[M,N] = A[M,K] @ W[N,K]^T + bias, optional exact gelu.
// Tiles: BM=64, BN=64, BK=32; 256 threads = 8 warps (2m x 4n), warp tile 32x16.
// Double-buffered cp.async; smem [row][k] with pad 4 (conflict-free frag LDS).
template <int ACT>
__global__ void __launch_bounds__(256, 2)
gemm_tf32(const float* __restrict__ A,
          const float* __restrict__ W,
          const float* __restrict__ bias,
          float* __restrict__ C,
          int M, int N, int K) {
    __shared__ float As[2][64*36];
    __shared__ float Bs[2][64*36];
    const int bn  = blockIdx.x * 64;
    const int bm  = blockIdx.y * 64;
    const int tid = threadIdx.x;
    const int warp = tid >> 5, lane = tid & 31;
    const int gid = lane >> 2, tig = lane & 3;
    const int m_warp = (warp & 1) * 32;
    const int n_warp = (warp >> 1) * 16;

    float acc[2][2][4];
    #pragma unroll
    for (int mi = 0; mi < 2; mi++)
        #pragma unroll
        for (int ni = 0; ni < 2; ni++)
            #pragma unroll
            for (int r = 0; r < 4; r++) acc[mi][ni][r] = 0.0f;

    const uint32_t a_base0 = (uint32_t)__cvta_generic_to_shared(&As[0][0]);
    const uint32_t b_base0 = (uint32_t)__cvta_generic_to_shared(&Bs[0][0]);

    auto load_tile = [&](int buf, int k0) {
        uint32_t a_base = a_base0 + buf * (64*36*4);
        uint32_t b_base = b_base0 + buf * (64*36*4);
        #pragma unroll
        for (int i = 0; i < 2; i++) {
            int idx = tid + i*256;           // 0..511
            int row = idx >> 3, q = idx & 7;
            int gr = bm + row;
            const float* src = A + (size_t)(gr < M ? gr : 0) * K + k0 + q*4;
            unsigned sz = (gr < M) ? 16u : 0u;
            asm volatile("cp.async.cg.shared.global [%0], [%1], 16, %2;"
                         :: "r"(a_base + (row*36 + q*4)*4), "l"(src), "r"(sz));
        }
        #pragma unroll
        for (int i = 0; i < 2; i++) {
            int idx = tid + i*256;
            int row = idx >> 3, q = idx & 7;
            const float* src = W + (size_t)(bn + row) * K + k0 + q*4;
            asm volatile("cp.async.cg.shared.global [%0], [%1], 16;"
                         :: "r"(b_base + (row*36 + q*4)*4), "l"(src));
        }
        asm volatile("cp.async.commit_group;");
    };

    const int T = K >> 5;
    load_tile(0, 0);
    for (int t = 0; t < T; t++) {
        int cur = t & 1;
        if (t + 1 < T) {
            load_tile(cur ^ 1, (t + 1) * 32);
            asm volatile("cp.async.wait_group 1;");
        } else {
            asm volatile("cp.async.wait_group 0;");
        }
        __syncthreads();
        const float* Ab = As[cur];
        const float* Bb = Bs[cur];
        #pragma unroll
        for (int kf = 0; kf < 4; kf++) {
            const int k8 = kf * 8;
            uint32_t ah[2][4], al[2][4];
            #pragma unroll
            for (int mi = 0; mi < 2; mi++) {
                int r = m_warp + mi*16 + gid;
                float v0 = Ab[r*36     + k8 + tig];
                float v1 = Ab[(r+8)*36 + k8 + tig];
                float v2 = Ab[r*36     + k8 + tig + 4];
                float v3 = Ab[(r+8)*36 + k8 + tig + 4];
                split_tf32(v0, ah[mi][0], al[mi][0]);
                split_tf32(v1, ah[mi][1], al[mi][1]);
                split_tf32(v2, ah[mi][2], al[mi][2]);
                split_tf32(v3, ah[mi][3], al[mi][3]);
            }
            uint32_t bh[2][2], bl[2][2];
            #pragma unroll
            for (int ni = 0; ni < 2; ni++) {
                int c = n_warp + ni*8 + gid;
                float w0 = Bb[c*36 + k8 + tig];
                float w1 = Bb[c*36 + k8 + tig + 4];
                split_tf32(w0, bh[ni][0], bl[ni][0]);
                split_tf32(w1, bh[ni][1], bl[ni][1]);
            }
            #pragma unroll
            for (int mi = 0; mi < 2; mi++)
                #pragma unroll
                for (int ni = 0; ni < 2; ni++) {
                    mma8(acc[mi][ni], ah[mi], bh[ni]);
                    mma8(acc[mi][ni], ah[mi], bl[ni]);
                    mma8(acc[mi][ni], al[mi], bh[ni]);
                }
        }
        __syncthreads();
    }

    // epilogue
    #pragma unroll
    for (int mi = 0; mi < 2; mi++) {
        #pragma unroll
        for (int ni = 0; ni < 2; ni++) {
            int col = bn + n_warp + ni*8 + tig*2;
            float b0v = bias[col], b1v = bias[col+1];
            float* a4 = acc[mi][ni];
            int r0 = bm + m_warp + mi*16 + gid;
            if (r0 < M) {
                float v0 = a4[0] + b0v, v1 = a4[1] + b1v;
                if (ACT) { v0 = gelu_exact(v0); v1 = gelu_exact(v1); }
                C[(size_t)r0*N + col]     = v0;
                C[(size_t)r0*N + col + 1] = v1;
            }
            int r1 = r0 + 8;
            if (r1 < M) {
                float v2 = a4[2] + b0v, v3 = a4[3] + b1v;
                if (ACT) { v2 = gelu_exact(v2); v3 = gelu_exact(v3); }
                C[(size_t)r1*N + col]     = v2;
                C[(size_t)r1*N + col + 1] = v3;
            }
        }
    }
}

// ---------------- attention: one block per (b, h) ----------------
__global__ void attn_kernel(const float* __restrict__ qkv, float* __restrict__ out) {
    int b = blockIdx.x, h = blockIdx.y;
    __shared__ float sk[NP1 * (DH + 1)];
    __shared__ float ss[NP1 * NP1];
    int tid = threadIdx.x;

    for (int idx = tid; idx < NP1*DH; idx += 256) {
        int t = idx >> 6, d = idx & 63;
        size_t base = (size_t)(b*NP1 + t) * (3*DD) + h*DH + d;
        sk[t*(DH+1) + d] = qkv[base + DD];
    }
    __syncthreads();

    const float scale = 0.125f;
    for (int idx = tid; idx < NP1*NP1; idx += 256) {
        int r = idx / NP1, c = idx - r*NP1;
        const float* q = qkv + (size_t)(b*NP1 + r) * (3*DD) + h*DH;
        const float* kk = sk + c*(DH+1);
        float s = 0.0f;
        #pragma unroll 16
        for (int d = 0; d < DH; d++) s = fmaf(__ldg(q + d), kk[d], s);
        ss[idx] = s * scale;
    }
    __syncthreads();

    if (tid < NP1) {
        float* row = ss + tid*NP1;
        float m = row[0];
        for (int j = 1; j < NP1; j++) m = fmaxf(m, row[j]);
        float sum = 0.0f;
        for (int j = 0; j < NP1; j++) { float e = __expf(row[j] - m); row[j] = e; sum += e; }
        float inv = 1.0f / sum;
        for (int j = 0; j < NP1; j++) row[j] *= inv;
    }
    __syncthreads();

    for (int idx = tid; idx < NP1*DH; idx += 256) {
        int r = idx >> 6, d = idx & 63;
        const float* row = ss + r*NP1;
        float o = 0.0f;
        #pragma unroll 5
        for (int t = 0; t < NP1; t++) {
            const float* v = qkv + (size_t)(b*NP1 + t) * (3*DD) + 2*DD + h*DH + d;
            o = fmaf(row[t], __ldg(v), o);
        }
        out[(size_t)(b*NP1 + r)*DD + h*DH + d] = o;
    }
}

// ---------------- residual add + layernorm (in-place on xs) ----------------
__global__ void resid_ln_kernel(float* __restrict__ xs,
                                const float* __restrict__ add,
                                const float* __restrict__ g,
                                const float* __restrict__ bb) {
    int t = blockIdx.x, tid = threadIdx.x;
    __shared__ float red[8];
    size_t base = (size_t)t * DD;
    float v0 = xs[base + tid]       + add[base + tid];
    float v1 = xs[base + tid + 256] + add[base + tid + 256];
    float s  = blockSum256(v0 + v1, red);
    float mu = s * (1.0f/512.0f);
    float d0 = v0 - mu, d1 = v1 - mu;
    float vs = blockSum256(d0*d0 + d1*d1, red);
    float inv = rsqrtf(vs * (1.0f/512.0f) + 1e-5f);
    xs[base + tid]       = d0*inv*g[tid]       + bb[tid];
    xs[base + tid + 256] = d1*inv*g[tid + 256] + bb[tid + 256];
}

// ---------------- final drift / correction -> h_pot ----------------
__global__ void hpot_kernel(const float* __restrict__ marg,
                            const float* __restrict__ xg,
                            float* __restrict__ out) {
    int b = blockIdx.x, n = blockIdx.y;
    int i = threadIdx.x;
    __shared__ float sx[256];
    __shared__ float red[8];
    sx[i] = xg[i];
    __syncthreads();

    float hr = g_hraw[(size_t)(b*NP1 + n)*MM + i];
    float xi = sx[i];
    float c  = hr * 100.0f;
    float m = fmaxf(c*(xi - sx[0]), c*(xi - sx[255]));
    float s0 = 0.0f, s1 = 0.0f;
    #pragma unroll 8
    for (int j = 0; j < 256; j++) {
        float xj = sx[j];
        float e = __expf(fmaf(c, xi - xj, -m));
        s0 += e;
        s1 = fmaf(e, xj, s1);
    }
    float drift = s1 / s0 - xi;
    float mu = marg[(size_t)(b*NP1 + n)*MM + i];
    float wd = blockSum256(mu * drift, red);
    float wm = blockSum256(mu, red);
    float corr = wd / (wm + 1e-8f);
    out[U_SIZE + (size_t)(b*64 + n)*MM + i] = hr - corr;
}

// ---------------- launch ----------------
extern "C" void kernel_launch(void* const* d_in, const int* in_sizes, int n_in,
                              void* d_out, int out_size) {
    const float* marg   = (const float*)d_in[0];
    const float* xg     = (const float*)d_in[1];
    const float* conv_w = (const float*)d_in[2];
    const float* conv_b = (const float*)d_in[3];
    const float* fc_w   = (const float*)d_in[4];
    const float* fc_b   = (const float*)d_in[5];
    const float* ln0_g  = (const float*)d_in[6];
    const float* ln0_b  = (const float*)d_in[7];
    const float* pos    = (const float*)d_in[8];
    const float* qkv_w  = (const float*)d_in[9];
    const float* qkv_b  = (const float*)d_in[10];
    const float* out_w  = (const float*)d_in[11];
    const float* out_b  = (const float*)d_in[12];
    const float* ln1_g  = (const float*)d_in[13];
    const float* ln1_b  = (const float*)d_in[14];
    const float* ff1_w  = (const float*)d_in[15];
    const float* ff1_b  = (const float*)d_in[16];
    const float* ff2_w  = (const float*)d_in[17];
    const float* ff2_b  = (const float*)d_in[18];
    const float* ln2_g  = (const float*)d_in[19];
    const float* ln2_b  = (const float*)d_in[20];
    const float* u_w    = (const float*)d_in[21];
    const float* u_b    = (const float*)d_in[22];
    const float* h_w    = (const float*)d_in[23];
    const float* h_b    = (const float*)d_in[24];
    float* out = (float*)d_out;

    float *xs, *qkvb, *attnb, *ffb, *hraw;
    cudaGetSymbolAddress((void**)&xs,    g_xs);
    cudaGetSymbolAddress((void**)&qkvb,  g_qkv);
    cudaGetSymbolAddress((void**)&attnb, g_attn);
    cudaGetSymbolAddress((void**)&ffb,   g_ff);
    cudaGetSymbolAddress((void**)&hraw,  g_hraw);

    const int GM = (NT + 63) / 64;   // 17

    embed_kernel<<<NT, 256>>>(marg, conv_w, conv_b, fc_w, fc_b, ln0_g, ln0_b, pos);

    for (int l = 0; l < LL; l++) {
        gemm_tf32<0><<<dim3((3*DD)/64, GM), 256>>>(
            xs, qkv_w + (size_t)l*3*DD*DD, qkv_b + (size_t)l*3*DD, qkvb, NT, 3*DD, DD);
        attn_kernel<<<dim3(BB, NH), 256>>>(qkvb, attnb);
        gemm_tf32<0><<<dim3(DD/64, GM), 256>>>(
            attnb, out_w + (size_t)l*DD*DD, out_b + (size_t)l*DD, qkvb, NT, DD, DD);
        resid_ln_kernel<<<NT, 256>>>(xs, qkvb, ln1_g + (size_t)l*DD, ln1_b + (size_t)l*DD);
        gemm_tf32<1><<<dim3(DFFN/64, GM), 256>>>(
            xs, ff1_w + (size_t)l*DFFN*DD, ff1_b + (size_t)l*DFFN, ffb, NT, DFFN, DD);
        gemm_tf32<0><<<dim3(DD/64, GM), 256>>>(
            ffb, ff2_w + (size_t)l*DD*DFFN, ff2_b + (size_t)l*DD, qkvb, NT, DD, DFFN);
        resid_ln_kernel<<<NT, 256>>>(xs, qkvb, ln2_g + (size_t)l*DD, ln2_b + (size_t)l*DD);
    }

    gemm_tf32<0><<<dim3(MM/64, GM), 256>>>(xs, u_w, u_b, out,  NT, MM, DD);
    gemm_tf32<0><<<dim3(MM/64, GM), 256>>>(xs, h_w, h_b, hraw, NT, MM, DD);

    hpot_kernel<<<dim3(BB, 64), 256>>>(marg, xg, out);
}

// round 4
// speedup vs baseline: 2.1203x; 1.2329x over previous
#include <cuda_runtime.h>
#include <cuda_bf16.h>
#include <math.h>
#include <stdint.h>

// ---------------- problem constants ----------------
#define BB    16
#define NP1   65
#define NT    (BB*NP1)      // 1040 tokens
#define MM    256
#define DD    512
#define NH    8
#define DH    64
#define LL    3
#define DFFN  2048
#define U_SIZE (NT*MM)

// weight-split buffer offsets (elements)
#define OFF_QKV 0
#define SZ_QKV  (LL*3*DD*DD)            // 2359296
#define OFF_OUT (OFF_QKV + SZ_QKV)
#define SZ_OUT  (LL*DD*DD)              // 786432
#define OFF_FF1 (OFF_OUT + SZ_OUT)
#define SZ_FF1  (LL*DFFN*DD)            // 3145728
#define OFF_FF2 (OFF_FF1 + SZ_FF1)
#define SZ_FF2  (LL*DD*DFFN)            // 3145728
#define OFF_U   (OFF_FF2 + SZ_FF2)
#define SZ_U    (MM*DD)                 // 131072
#define OFF_H   (OFF_U + SZ_U)
#define SZ_H    (MM*DD)
#define WTOT    (OFF_H + SZ_H)          // 9699328

// ---------------- scratch ----------------
__device__ float        g_xs  [NT*DD];
__device__ __nv_bfloat16 g_xshi[NT*DD];
__device__ __nv_bfloat16 g_xslo[NT*DD];
__device__ float        g_buf [NT*3*DD];     // qkv fp32 / proj-out / ff2-out
__device__ __nv_bfloat16 g_athi[NT*DD];
__device__ __nv_bfloat16 g_atlo[NT*DD];
__device__ __nv_bfloat16 g_ffhi[NT*DFFN];
__device__ __nv_bfloat16 g_fflo[NT*DFFN];
__device__ float        g_hraw[NT*MM];
__device__ __nv_bfloat16 g_whi[WTOT];
__device__ __nv_bfloat16 g_wlo[WTOT];

// ---------------- helpers ----------------
__device__ __forceinline__ float gelu_exact(float x) {
    return 0.5f * x * (1.0f + erff(x * 0.70710678118654752440f));
}
__device__ __forceinline__ void bsplit(float x, __nv_bfloat16& h, __nv_bfloat16& l) {
    h = __float2bfloat16_rn(x);
    l = __float2bfloat16_rn(x - __bfloat162float(h));
}
__device__ __forceinline__ float blockSum256(float v, float* sm) {
    int tid = threadIdx.x;
    #pragma unroll
    for (int o = 16; o > 0; o >>= 1) v += __shfl_down_sync(0xffffffffu, v, o);
    if ((tid & 31) == 0) sm[tid >> 5] = v;
    __syncthreads();
    if (tid < 8) {
        v = sm[tid];
        #pragma unroll
        for (int o = 4; o > 0; o >>= 1) v += __shfl_down_sync(0xffu, v, o);
        if (tid == 0) sm[0] = v;
    }
    __syncthreads();
    float r = sm[0];
    __syncthreads();
    return r;
}
__device__ __forceinline__ void mma16(float* d, const uint32_t* a, const uint32_t* b) {
    asm volatile(
        "mma.sync.aligned.m16n8k16.row.col.f32.bf16.bf16.f32 "
        "{%0,%1,%2,%3}, {%4,%5,%6,%7}, {%8,%9}, {%0,%1,%2,%3};"
        : "+f"(d[0]), "+f"(d[1]), "+f"(d[2]), "+f"(d[3])
        : "r"(a[0]), "r"(a[1]), "r"(a[2]), "r"(a[3]), "r"(b[0]), "r"(b[1]));
}

// ---------------- weight split (float4 vectorized) ----------------
__global__ void split_kernel(const float4* __restrict__ src,
                             __nv_bfloat162* __restrict__ hi,
                             __nv_bfloat162* __restrict__ lo, int n4) {
    for (int i = blockIdx.x*blockDim.x + threadIdx.x; i < n4; i += gridDim.x*blockDim.x) {
        float4 v = src[i];
        __nv_bfloat16 hx, lx, hy, ly, hz, lz, hw, lw;
        bsplit(v.x, hx, lx); bsplit(v.y, hy, ly);
        bsplit(v.z, hz, lz); bsplit(v.w, hw, lw);
        hi[2*i]   = __nv_bfloat162(hx, hy);
        hi[2*i+1] = __nv_bfloat162(hz, hw);
        lo[2*i]   = __nv_bfloat162(lx, ly);
        lo[2*i+1] = __nv_bfloat162(lz, lw);
    }
}

// ---------------- embed ----------------
__global__ void embed_kernel(const float* __restrict__ marg,
                             const float* __restrict__ conv_w,
                             const float* __restrict__ conv_b,
                             const float* __restrict__ fc_w,
                             const float* __restrict__ fc_b,
                             const float* __restrict__ ln_g,
                             const float* __restrict__ ln_b,
                             const float* __restrict__ pos) {
    int t   = blockIdx.x;
    int tid = threadIdx.x;
    __shared__ float red[8];
    __shared__ float e128[128];

    const float* x = marg + (size_t)t * MM;
    float S = blockSum256(x[tid], red);

    if (tid < 128) {
        float x0 = x[0], x1 = x[1], x254 = x[254], x255 = x[255];
        float T0 = S - x254 - x255;
        float T1 = S - x255;
        float T2 = S;
        float T3 = S - x0;
        float T4 = S - x0 - x1;
        const float* w = conv_w + tid * 5;
        e128[tid] = conv_b[tid] +
            (w[0]*T0 + w[1]*T1 + w[2]*T2 + w[3]*T3 + w[4]*T4) * (1.0f/256.0f);
    }
    __syncthreads();

    float y0 = fc_b[tid];
    float y1 = fc_b[tid + 256];
    #pragma unroll 8
    for (int k = 0; k < 128; k++) {
        float e = e128[k];
        y0 = fmaf(e, fc_w[k*DD + tid],       y0);
        y1 = fmaf(e, fc_w[k*DD + tid + 256], y1);
    }
    float s  = blockSum256(y0 + y1, red);
    float mu = s * (1.0f/512.0f);
    float d0 = y0 - mu, d1 = y1 - mu;
    float vs = blockSum256(d0*d0 + d1*d1, red);
    float inv = rsqrtf(vs * (1.0f/512.0f) + 1e-5f);

    int p = t % NP1;
    float z0 = gelu_exact(d0*inv*ln_g[tid]       + ln_b[tid])       + pos[p*DD + tid];
    float z1 = gelu_exact(d1*inv*ln_g[tid + 256] + ln_b[tid + 256]) + pos[p*DD + tid + 256];
    size_t i0 = (size_t)t*DD + tid, i1 = i0 + 256;
    g_xs[i0] = z0; g_xs[i1] = z1;
    __nv_bfloat16 h, l;
    bsplit(z0, h, l); g_xshi[i0] = h; g_xslo[i0] = l;
    bsplit(z1, h, l); g_xshi[i1] = h; g_xslo[i1] = l;
}

// ---------------- 3xBF16 tensor-core GEMM ----------------
// C[M,N] = A[M,K] @ W[N,K]^T + bias; MODE 0: fp32 store; MODE 1: gelu + split store.
// BM=BN=64, BK=32, 256 thr = 8 warps (2m x 4n), warp tile 32x16 (m16n8k16 x 2x2 x3).
#define SST 40   // smem row stride (halves)
template <int MODE>
__global__ void __launch_bounds__(256, 2)
gemm_bf16(const __nv_bfloat16* __restrict__ Ahi, const __nv_bfloat16* __restrict__ Alo,
          const __nv_bfloat16* __restrict__ Whi, const __nv_bfloat16* __restrict__ Wlo,
          const float* __restrict__ bias,
          float* __restrict__ C,
          __nv_bfloat16* __restrict__ Chi, __nv_bfloat16* __restrict__ Clo,
          int M, int N, int K) {
    __shared__ __nv_bfloat16 smbuf[2][4][64*SST];   // [buf][Ah,Al,Bh,Bl]
    const int bn  = blockIdx.x * 64;
    const int bm  = blockIdx.y * 64;
    const int tid = threadIdx.x;
    const int warp = tid >> 5, lane = tid & 31;
    const int gid = lane >> 2, tig = lane & 3;
    const int m_warp = (warp & 1) * 32;
    const int n_warp = (warp >> 1) * 16;

    float acc[2][2][4];
    #pragma unroll
    for (int mi = 0; mi < 2; mi++)
        #pragma unroll
        for (int ni = 0; ni < 2; ni++)
            #pragma unroll
            for (int r = 0; r < 4; r++) acc[mi][ni][r] = 0.0f;

    const uint32_t s_base = (uint32_t)__cvta_generic_to_shared(&smbuf[0][0][0]);
    const int row = tid >> 2;         // 0..63
    const int q   = tid & 3;          // 0..3
    const int gr  = bm + row;
    const unsigned a_ok = (gr < M) ? 16u : 0u;
    const size_t aoff = (size_t)(gr < M ? gr : 0) * K + q*8;
    const size_t boff = (size_t)(bn + row) * K + q*8;
    const uint32_t dsto = (uint32_t)(row*SST + q*8) * 2;

    auto load_tile = [&](int buf, int k0) {
        uint32_t base = s_base + (uint32_t)buf * (4*64*SST*2);
        asm volatile("cp.async.cg.shared.global [%0], [%1], 16, %2;"
                     :: "r"(base + dsto), "l"(Ahi + aoff + k0), "r"(a_ok));
        asm volatile("cp.async.cg.shared.global [%0], [%1], 16, %2;"
                     :: "r"(base + 64*SST*2 + dsto), "l"(Alo + aoff + k0), "r"(a_ok));
        asm volatile("cp.async.cg.shared.global [%0], [%1], 16;"
                     :: "r"(base + 2*64*SST*2 + dsto), "l"(Whi + boff + k0));
        asm volatile("cp.async.cg.shared.global [%0], [%1], 16;"
                     :: "r"(base + 3*64*SST*2 + dsto), "l"(Wlo + boff + k0));
        asm volatile("cp.async.commit_group;");
    };

    const int T = K >> 5;
    load_tile(0, 0);
    for (int t = 0; t < T; t++) {
        int cur = t & 1;
        if (t + 1 < T) {
            load_tile(cur ^ 1, (t + 1) * 32);
            asm volatile("cp.async.wait_group 1;");
        } else {
            asm volatile("cp.async.wait_group 0;");
        }
        __syncthreads();
        const __nv_bfloat16* Ah = smbuf[cur][0];
        const __nv_bfloat16* Al = smbuf[cur][1];
        const __nv_bfloat16* Bh = smbuf[cur][2];
        const __nv_bfloat16* Bl = smbuf[cur][3];
        #pragma unroll
        for (int kf = 0; kf < 2; kf++) {
            const int kb = kf*16 + 2*tig;
            uint32_t ah[2][4], al[2][4];
            #pragma unroll
            for (int mi = 0; mi < 2; mi++) {
                int r0 = m_warp + mi*16 + gid;
                ah[mi][0] = *(const uint32_t*)&Ah[r0*SST + kb];
                ah[mi][1] = *(const uint32_t*)&Ah[(r0+8)*SST + kb];
                ah[mi][2] = *(const uint32_t*)&Ah[r0*SST + kb + 8];
                ah[mi][3] = *(const uint32_t*)&Ah[(r0+8)*SST + kb + 8];
                al[mi][0] = *(const uint32_t*)&Al[r0*SST + kb];
                al[mi][1] = *(const uint32_t*)&Al[(r0+8)*SST + kb];
                al[mi][2] = *(const uint32_t*)&Al[r0*SST + kb + 8];
                al[mi][3] = *(const uint32_t*)&Al[(r0+8)*SST + kb + 8];
            }
            uint32_t bh[2][2], bl[2][2];
            #pragma unroll
            for (int ni = 0; ni < 2; ni++) {
                int c0 = n_warp + ni*8 + gid;
                bh[ni][0] = *(const uint32_t*)&Bh[c0*SST + kb];
                bh[ni][1] = *(const uint32_t*)&Bh[c0*SST + kb + 8];
                bl[ni][0] = *(const uint32_t*)&Bl[c0*SST + kb];
                bl[ni][1] = *(const uint32_t*)&Bl[c0*SST + kb + 8];
            }
            #pragma unroll
            for (int mi = 0; mi < 2; mi++)
                #pragma unroll
                for (int ni = 0; ni < 2; ni++) {
                    mma16(acc[mi][ni], ah[mi], bh[ni]);
                    mma16(acc[mi][ni], ah[mi], bl[ni]);
                    mma16(acc[mi][ni], al[mi], bh[ni]);
                }
        }
        __syncthreads();
    }

    #pragma unroll
    for (int mi = 0; mi < 2; mi++) {
        #pragma unroll
        for (int ni = 0; ni < 2; ni++) {
            int col = bn + n_warp + ni*8 + tig*2;
            float b0v = bias[col], b1v = bias[col+1];
            float* a4 = acc[mi][ni];
            #pragma unroll
            for (int half = 0; half < 2; half++) {
                int r0 = bm + m_warp + mi*16 + gid + half*8;
                if (r0 >= M) continue;
                float v0 = a4[half*2]   + b0v;
                float v1 = a4[half*2+1] + b1v;
                if (MODE == 0) {
                    C[(size_t)r0*N + col]     = v0;
                    C[(size_t)r0*N + col + 1] = v1;
                } else {
                    v0 = gelu_exact(v0); v1 = gelu_exact(v1);
                    __nv_bfloat16 h0, l0, h1, l1;
                    bsplit(v0, h0, l0); bsplit(v1, h1, l1);
                    *(__nv_bfloat162*)&Chi[(size_t)r0*N + col] = __nv_bfloat162(h0, h1);
                    *(__nv_bfloat162*)&Clo[(size_t)r0*N + col] = __nv_bfloat162(l0, l1);
                }
            }
        }
    }
}

// ---------------- attention: one block per (b, h); writes split-bf16 ----------------
__global__ void attn_kernel(const float* __restrict__ qkv) {
    int b = blockIdx.x, h = blockIdx.y;
    __shared__ float sk[NP1 * (DH + 1)];
    __shared__ float ss[NP1 * 66];
    int tid = threadIdx.x;
    int warp = tid >> 5, lane = tid & 31;

    for (int idx = tid; idx < NP1*DH; idx += 256) {
        int t = idx >> 6, d = idx & 63;
        size_t base = (size_t)(b*NP1 + t) * (3*DD) + h*DH + d;
        sk[t*(DH+1) + d] = qkv[base + DD];
    }
    __syncthreads();

    const float scale = 0.125f;
    for (int idx = tid; idx < NP1*NP1; idx += 256) {
        int r = idx / NP1, c = idx - r*NP1;
        const float* qp = qkv + (size_t)(b*NP1 + r) * (3*DD) + h*DH;
        const float* kk = sk + c*(DH+1);
        float s = 0.0f;
        #pragma unroll 16
        for (int d = 0; d < DH; d++) s = fmaf(__ldg(qp + d), kk[d], s);
        ss[r*66 + c] = s * scale;
    }
    __syncthreads();

    // warp-parallel softmax: warp w handles rows w, w+8, ...
    for (int r = warp; r < NP1; r += 8) {
        float* rowp = ss + r*66;
        float m = -1e30f;
        for (int c = lane; c < NP1; c += 32) m = fmaxf(m, rowp[c]);
        #pragma unroll
        for (int o = 16; o > 0; o >>= 1) m = fmaxf(m, __shfl_xor_sync(0xffffffffu, m, o));
        float s = 0.0f;
        for (int c = lane; c < NP1; c += 32) { float e = __expf(rowp[c] - m); rowp[c] = e; s += e; }
        #pragma unroll
        for (int o = 16; o > 0; o >>= 1) s += __shfl_xor_sync(0xffffffffu, s, o);
        float inv = 1.0f / s;
        for (int c = lane; c < NP1; c += 32) rowp[c] *= inv;
    }
    __syncthreads();

    for (int idx = tid; idx < NP1*DH; idx += 256) {
        int r = idx >> 6, d = idx & 63;
        const float* rowp = ss + r*66;
        float o = 0.0f;
        #pragma unroll 5
        for (int t = 0; t < NP1; t++) {
            const float* v = qkv + (size_t)(b*NP1 + t) * (3*DD) + 2*DD + h*DH + d;
            o = fmaf(rowp[t], __ldg(v), o);
        }
        size_t gi = (size_t)(b*NP1 + r)*DD + h*DH + d;
        __nv_bfloat16 hh, ll;
        bsplit(o, hh, ll);
        g_athi[gi] = hh; g_atlo[gi] = ll;
    }
}

// ---------------- residual add + layernorm; writes fp32 + split ----------------
__global__ void resid_ln_kernel(float* __restrict__ xs,
                                const float* __restrict__ add,
                                const float* __restrict__ g,
                                const float* __restrict__ bb) {
    int t = blockIdx.x, tid = threadIdx.x;
    __shared__ float red[8];
    size_t base = (size_t)t * DD;
    float v0 = xs[base + tid]       + add[base + tid];
    float v1 = xs[base + tid + 256] + add[base + tid + 256];
    float s  = blockSum256(v0 + v1, red);
    float mu = s * (1.0f/512.0f);
    float d0 = v0 - mu, d1 = v1 - mu;
    float vs = blockSum256(d0*d0 + d1*d1, red);
    float inv = rsqrtf(vs * (1.0f/512.0f) + 1e-5f);
    float z0 = d0*inv*g[tid]       + bb[tid];
    float z1 = d1*inv*g[tid + 256] + bb[tid + 256];
    xs[base + tid]       = z0;
    xs[base + tid + 256] = z1;
    __nv_bfloat16 h, l;
    bsplit(z0, h, l); g_xshi[base + tid] = h;       g_xslo[base + tid] = l;
    bsplit(z1, h, l); g_xshi[base + tid + 256] = h; g_xslo[base + tid + 256] = l;
}

// ---------------- final drift / correction -> h_pot (closed-form geometric softmax) ----------------
__global__ void hpot_kernel(const float* __restrict__ marg,
                            const float* __restrict__ xg,
                            float* __restrict__ out) {
    int b = blockIdx.x, n = blockIdx.y;
    int i = threadIdx.x;
    __shared__ float red[8];

    float x0   = __ldg(xg);
    float xend = __ldg(xg + 255);
    float delta = (xend - x0) * (1.0f/255.0f);
    float xi = __ldg(xg + i);

    float hr = g_hraw[(size_t)(b*NP1 + n)*MM + i];
    float u  = hr * 100.0f * delta;     // logit decay per grid step
    float Mv;
    if (fabsf(u) < 1e-3f) {
        Mv = 127.5f - u*5461.25f + u*u*u*5965232.4f;
    } else {
        Mv = 1.0f/expm1f(u) - 256.0f/expm1f(256.0f*u);
    }
    float drift = (x0 + delta*Mv) - xi;

    float mu = marg[(size_t)(b*NP1 + n)*MM + i];
    float wd = blockSum256(mu * drift, red);
    float wm = blockSum256(mu, red);
    float corr = wd / (wm + 1e-8f);
    out[U_SIZE + (size_t)(b*64 + n)*MM + i] = hr - corr;
}

// ---------------- launch ----------------
extern "C" void kernel_launch(void* const* d_in, const int* in_sizes, int n_in,
                              void* d_out, int out_size) {
    const float* marg   = (const float*)d_in[0];
    const float* xg     = (const float*)d_in[1];
    const float* conv_w = (const float*)d_in[2];
    const float* conv_b = (const float*)d_in[3];
    const float* fc_w   = (const float*)d_in[4];
    const float* fc_b   = (const float*)d_in[5];
    const float* ln0_g  = (const float*)d_in[6];
    const float* ln0_b  = (const float*)d_in[7];
    const float* pos    = (const float*)d_in[8];
    const float* qkv_w  = (const float*)d_in[9];
    const float* qkv_b  = (const float*)d_in[10];
    const float* out_w  = (const float*)d_in[11];
    const float* out_b  = (const float*)d_in[12];
    const float* ln1_g  = (const float*)d_in[13];
    const float* ln1_b  = (const float*)d_in[14];
    const float* ff1_w  = (const float*)d_in[15];
    const float* ff1_b  = (const float*)d_in[16];
    const float* ff2_w  = (const float*)d_in[17];
    const float* ff2_b  = (const float*)d_in[18];
    const float* ln2_g  = (const float*)d_in[19];
    const float* ln2_b  = (const float*)d_in[20];
    const float* u_w    = (const float*)d_in[21];
    const float* u_b    = (const float*)d_in[22];
    const float* h_w    = (const float*)d_in[23];
    const float* h_b    = (const float*)d_in[24];
    float* out = (float*)d_out;

    float *xs, *buf, *hraw;
    __nv_bfloat16 *xshi, *xslo, *athi, *atlo, *ffhi, *fflo, *whi, *wlo;
    cudaGetSymbolAddress((void**)&xs,   g_xs);
    cudaGetSymbolAddress((void**)&buf,  g_buf);
    cudaGetSymbolAddress((void**)&hraw, g_hraw);
    cudaGetSymbolAddress((void**)&xshi, g_xshi);
    cudaGetSymbolAddress((void**)&xslo, g_xslo);
    cudaGetSymbolAddress((void**)&athi, g_athi);
    cudaGetSymbolAddress((void**)&atlo, g_atlo);
    cudaGetSymbolAddress((void**)&ffhi, g_ffhi);
    cudaGetSymbolAddress((void**)&fflo, g_fflo);
    cudaGetSymbolAddress((void**)&whi,  g_whi);
    cudaGetSymbolAddress((void**)&wlo,  g_wlo);

    // weight pre-split
    auto split = [&](const float* src, size_t off, int n) {
        int n4 = n >> 2;
        int grid = (n4 + 255) / 256; if (grid > 4096) grid = 4096;
        split_kernel<<<grid, 256>>>((const float4*)src,
            (__nv_bfloat162*)(whi + off), (__nv_bfloat162*)(wlo + off), n4);
    };
    split(qkv_w, OFF_QKV, SZ_QKV);
    split(out_w, OFF_OUT, SZ_OUT);
    split(ff1_w, OFF_FF1, SZ_FF1);
    split(ff2_w, OFF_FF2, SZ_FF2);
    split(u_w,   OFF_U,   SZ_U);
    split(h_w,   OFF_H,   SZ_H);

    const int GM = (NT + 63) / 64;   // 17

    embed_kernel<<<NT, 256>>>(marg, conv_w, conv_b, fc_w, fc_b, ln0_g, ln0_b, pos);

    for (int l = 0; l < LL; l++) {
        gemm_bf16<0><<<dim3((3*DD)/64, GM), 256>>>(
            xshi, xslo, whi + OFF_QKV + (size_t)l*3*DD*DD, wlo + OFF_QKV + (size_t)l*3*DD*DD,
            qkv_b + (size_t)l*3*DD, buf, nullptr, nullptr, NT, 3*DD, DD);
        attn_kernel<<<dim3(BB, NH), 256>>>(buf);
        gemm_bf16<0><<<dim3(DD/64, GM), 256>>>(
            athi, atlo, whi + OFF_OUT + (size_t)l*DD*DD, wlo + OFF_OUT + (size_t)l*DD*DD,
            out_b + (size_t)l*DD, buf, nullptr, nullptr, NT, DD, DD);
        resid_ln_kernel<<<NT, 256>>>(xs, buf, ln1_g + (size_t)l*DD, ln1_b + (size_t)l*DD);
        gemm_bf16<1><<<dim3(DFFN/64, GM), 256>>>(
            xshi, xslo, whi + OFF_FF1 + (size_t)l*DFFN*DD, wlo + OFF_FF1 + (size_t)l*DFFN*DD,
            ff1_b + (size_t)l*DFFN, nullptr, ffhi, fflo, NT, DFFN, DD);
        gemm_bf16<0><<<dim3(DD/64, GM), 256>>>(
            ffhi, fflo, whi + OFF_FF2 + (size_t)l*DD*DFFN, wlo + OFF_FF2 + (size_t)l*DD*DFFN,
            ff2_b + (size_t)l*DD, buf, nullptr, nullptr, NT, DD, DFFN);
        resid_ln_kernel<<<NT, 256>>>(xs, buf, ln2_g + (size_t)l*DD, ln2_b + (size_t)l*DD);
    }

    gemm_bf16<0><<<dim3(MM/64, GM), 256>>>(
        xshi, xslo, whi + OFF_U, wlo + OFF_U, u_b, out,  nullptr, nullptr, NT, MM, DD);
    gemm_bf16<0><<<dim3(MM/64, GM), 256>>>(
        xshi, xslo, whi + OFF_H, wlo + OFF_H, h_b, hraw, nullptr, nullptr, NT, MM, DD);

    hpot_kernel<<<dim3(BB, 64), 256>>>(marg, xg, out);
}

// round 6
// speedup vs baseline: 2.1324x; 1.0057x over previous
#include <cuda_runtime.h>
#include <cuda_bf16.h>
#include <math.h>
#include <stdint.h>

// ---------------- problem constants ----------------
#define BB    16
#define NP1   65
#define NT    (BB*NP1)      // 1040 tokens
#define MM    256
#define DD    512
#define NH    8
#define DH    64
#define LL    3
#define DFFN  2048
#define U_SIZE (NT*MM)

// weight-split buffer offsets (elements)
#define OFF_QKV 0
#define SZ_QKV  (LL*3*DD*DD)
#define OFF_OUT (OFF_QKV + SZ_QKV)
#define SZ_OUT  (LL*DD*DD)
#define OFF_FF1 (OFF_OUT + SZ_OUT)
#define SZ_FF1  (LL*DFFN*DD)
#define OFF_FF2 (OFF_FF1 + SZ_FF1)
#define SZ_FF2  (LL*DD*DFFN)
#define OFF_U   (OFF_FF2 + SZ_FF2)
#define SZ_U    (MM*DD)
#define OFF_H   (OFF_U + SZ_U)
#define SZ_H    (MM*DD)
#define WTOT    (OFF_H + SZ_H)

// ---------------- scratch ----------------
__device__ float         g_xs  [NT*DD];
__device__ __nv_bfloat16 g_xshi[NT*DD];
__device__ __nv_bfloat16 g_xslo[NT*DD];
__device__ float         g_buf [NT*3*DD];
__device__ __nv_bfloat16 g_athi[NT*DD];
__device__ __nv_bfloat16 g_atlo[NT*DD];
__device__ __nv_bfloat16 g_ffhi[NT*DFFN];
__device__ __nv_bfloat16 g_fflo[NT*DFFN];
__device__ float         g_hraw[NT*MM];
__device__ __nv_bfloat16 g_whi[WTOT];
__device__ __nv_bfloat16 g_wlo[WTOT];

// ---------------- helpers ----------------
__device__ __forceinline__ float gelu_exact(float x) {
    return 0.5f * x * (1.0f + erff(x * 0.70710678118654752440f));
}
__device__ __forceinline__ void bsplit(float x, __nv_bfloat16& h, __nv_bfloat16& l) {
    h = __float2bfloat16_rn(x);
    l = __float2bfloat16_rn(x - __bfloat162float(h));
}
__device__ __forceinline__ float blockSum256(float v, float* sm) {
    int tid = threadIdx.x;
    #pragma unroll
    for (int o = 16; o > 0; o >>= 1) v += __shfl_down_sync(0xffffffffu, v, o);
    if ((tid & 31) == 0) sm[tid >> 5] = v;
    __syncthreads();
    if (tid < 8) {
        v = sm[tid];
        #pragma unroll
        for (int o = 4; o > 0; o >>= 1) v += __shfl_down_sync(0xffu, v, o);
        if (tid == 0) sm[0] = v;
    }
    __syncthreads();
    float r = sm[0];
    __syncthreads();
    return r;
}
__device__ __forceinline__ void mma16(float* d, const uint32_t* a, const uint32_t* b) {
    asm volatile(
        "mma.sync.aligned.m16n8k16.row.col.f32.bf16.bf16.f32 "
        "{%0,%1,%2,%3}, {%4,%5,%6,%7}, {%8,%9}, {%0,%1,%2,%3};"
        : "+f"(d[0]), "+f"(d[1]), "+f"(d[2]), "+f"(d[3])
        : "r"(a[0]), "r"(a[1]), "r"(a[2]), "r"(a[3]), "r"(b[0]), "r"(b[1]));
}
__device__ __forceinline__ uint32_t smem_u32(const void* p) {
    uint32_t a;
    asm("{ .reg .u64 t; cvta.to.shared.u64 t, %1; cvt.u32.u64 %0, t; }" : "=r"(a) : "l"(p));
    return a;
}
__device__ __forceinline__ void cp16(uint32_t dst, const void* src, unsigned ok) {
    asm volatile("cp.async.cg.shared.global [%0], [%1], 16, %2;"
                 :: "r"(dst), "l"(src), "r"(ok));
}
__device__ __forceinline__ void cp16u(uint32_t dst, const void* src) {
    asm volatile("cp.async.cg.shared.global [%0], [%1], 16;"
                 :: "r"(dst), "l"(src));
}

// ---------------- fused weight split ----------------
#define B0 (SZ_QKV/4)
#define B1 (B0 + SZ_OUT/4)
#define B2 (B1 + SZ_FF1/4)
#define B3 (B2 + SZ_FF2/4)
#define B4 (B3 + SZ_U/4)
#define B5 (B4 + SZ_H/4)
__global__ void split_all(const float4* __restrict__ w_qkv, const float4* __restrict__ w_out,
                          const float4* __restrict__ w_ff1, const float4* __restrict__ w_ff2,
                          const float4* __restrict__ w_u,   const float4* __restrict__ w_h) {
    __nv_bfloat162* hi = (__nv_bfloat162*)g_whi;
    __nv_bfloat162* lo = (__nv_bfloat162*)g_wlo;
    for (int i = blockIdx.x*blockDim.x + threadIdx.x; i < B5; i += gridDim.x*blockDim.x) {
        const float4* src; int j;
        if      (i < B0) { src = w_qkv; j = i; }
        else if (i < B1) { src = w_out; j = i - B0; }
        else if (i < B2) { src = w_ff1; j = i - B1; }
        else if (i < B3) { src = w_ff2; j = i - B2; }
        else if (i < B4) { src = w_u;   j = i - B3; }
        else             { src = w_h;   j = i - B4; }
        float4 v = src[j];
        __nv_bfloat16 hx, lx, hy, ly, hz, lz, hw, lw;
        bsplit(v.x, hx, lx); bsplit(v.y, hy, ly);
        bsplit(v.z, hz, lz); bsplit(v.w, hw, lw);
        hi[2*i]   = __nv_bfloat162(hx, hy);
        hi[2*i+1] = __nv_bfloat162(hz, hw);
        lo[2*i]   = __nv_bfloat162(lx, ly);
        lo[2*i+1] = __nv_bfloat162(lz, lw);
    }
}

// ---------------- embed ----------------
__global__ void embed_kernel(const float* __restrict__ marg,
                             const float* __restrict__ conv_w,
                             const float* __restrict__ conv_b,
                             const float* __restrict__ fc_w,
                             const float* __restrict__ fc_b,
                             const float* __restrict__ ln_g,
                             const float* __restrict__ ln_b,
                             const float* __restrict__ pos) {
    int t   = blockIdx.x;
    int tid = threadIdx.x;
    __shared__ float red[8];
    __shared__ float e128[128];

    const float* x = marg + (size_t)t * MM;
    float S = blockSum256(x[tid], red);

    if (tid < 128) {
        float x0 = x[0], x1 = x[1], x254 = x[254], x255 = x[255];
        float T0 = S - x254 - x255;
        float T1 = S - x255;
        float T2 = S;
        float T3 = S - x0;
        float T4 = S - x0 - x1;
        const float* w = conv_w + tid * 5;
        e128[tid] = conv_b[tid] +
            (w[0]*T0 + w[1]*T1 + w[2]*T2 + w[3]*T3 + w[4]*T4) * (1.0f/256.0f);
    }
    __syncthreads();

    float y0 = fc_b[tid];
    float y1 = fc_b[tid + 256];
    #pragma unroll 8
    for (int k = 0; k < 128; k++) {
        float e = e128[k];
        y0 = fmaf(e, fc_w[k*DD + tid],       y0);
        y1 = fmaf(e, fc_w[k*DD + tid + 256], y1);
    }
    float s  = blockSum256(y0 + y1, red);
    float mu = s * (1.0f/512.0f);
    float d0 = y0 - mu, d1 = y1 - mu;
    float vs = blockSum256(d0*d0 + d1*d1, red);
    float inv = rsqrtf(vs * (1.0f/512.0f) + 1e-5f);

    int p = t % NP1;
    float z0 = gelu_exact(d0*inv*ln_g[tid]       + ln_b[tid])       + pos[p*DD + tid];
    float z1 = gelu_exact(d1*inv*ln_g[tid + 256] + ln_b[tid + 256]) + pos[p*DD + tid + 256];
    size_t i0 = (size_t)t*DD + tid, i1 = i0 + 256;
    g_xs[i0] = z0; g_xs[i1] = z1;
    __nv_bfloat16 h, l;
    bsplit(z0, h, l); g_xshi[i0] = h; g_xslo[i0] = l;
    bsplit(z1, h, l); g_xshi[i1] = h; g_xslo[i1] = l;
}

// ---------------- 3xBF16 mma.sync GEMM, BM=128 ----------------
// C[M,N] = A[M,K] @ W[N,K]^T + bias.
// MODE 0: fp32 + bias. MODE 1: gelu + bf16 hi/lo split. MODE 2: dual heads (u/h).
// BK=32, 3-stage cp.async ring, 256 threads = 8 warps (4m x 2n), warp tile 32 x BN/2.
#define SSTH 40                      // smem row stride in halves (80B, /16B ok)
template <int BN, int MODE>
__global__ void __launch_bounds__(256, 2)
gemm_bf16(const __nv_bfloat16* __restrict__ Ahi, const __nv_bfloat16* __restrict__ Alo,
          const __nv_bfloat16* __restrict__ Whi, const __nv_bfloat16* __restrict__ Wlo,
          const float* __restrict__ bias, const float* __restrict__ bias2,
          float* __restrict__ C, __nv_bfloat16* __restrict__ Chi, __nv_bfloat16* __restrict__ Clo,
          float* __restrict__ C2,
          int M, int N, int K) {
    constexpr int MFRAG = 2;
    constexpr int NFRAG = BN / 16;               // 4 (BN=64) or 2 (BN=32)
    constexpr int AH_E  = 128 * SSTH;            // halves per A array
    constexpr int BH_E  = BN * SSTH;
    constexpr int STAGE_E = 2*AH_E + 2*BH_E;     // halves per stage

    extern __shared__ __align__(16) __nv_bfloat16 sm[];
    const int tid  = threadIdx.x;
    const int warp = tid >> 5, lane = tid & 31;
    const int gid  = lane >> 2, tig = lane & 3;
    const int m_warp = (warp & 3) * 32;
    const int n_warp = (warp >> 2) * (BN/2);
    const int bn = blockIdx.x * BN;
    const int bm = blockIdx.y * 128;

    float acc[MFRAG][NFRAG][4];
    #pragma unroll
    for (int mi = 0; mi < MFRAG; mi++)
        #pragma unroll
        for (int ni = 0; ni < NFRAG; ni++)
            #pragma unroll
            for (int r = 0; r < 4; r++) acc[mi][ni][r] = 0.0f;

    const uint32_t smb = smem_u32(sm);

    // per-thread load coords
    const int rowA = tid >> 2;          // 0..63
    const int chkA = tid & 3;           // 16B chunk (8 halves)
    const int T = K >> 5;

    auto load_tile = [&](int stage, int k0) {
        uint32_t sb = smb + (uint32_t)stage * (STAGE_E*2);
        #pragma unroll
        for (int i = 0; i < 2; i++) {
            int row = rowA + i*64;
            int gr  = bm + row;
            unsigned ok = (gr < M) ? 16u : 0u;
            size_t go = (size_t)(gr < M ? gr : 0) * K + k0 + chkA*8;
            uint32_t d = sb + (uint32_t)(row*SSTH + chkA*8)*2;
            cp16(d,            Ahi + go, ok);
            cp16(d + AH_E*2,   Alo + go, ok);
        }
        {
            int nb = BN * 4;            // 16B chunks in B tile
            if (BN == 64 || tid < nb) {
                int row = (BN == 64) ? rowA : (tid >> 2);
                int chk = (BN == 64) ? chkA : (tid & 3);
                size_t go = (size_t)(bn + row) * K + k0 + chk*8;
                uint32_t d = sb + (uint32_t)(2*AH_E + row*SSTH + chk*8)*2;
                cp16u(d,          Whi + go);
                cp16u(d + BH_E*2, Wlo + go);
            }
        }
        asm volatile("cp.async.commit_group;");
    };

    load_tile(0, 0);
    if (T > 1) load_tile(1, 32);

    for (int t = 0; t < T; t++) {
        if (t + 2 < T) load_tile((t + 2) % 3, (t + 2) * 32);
        int rem = T - 1 - t; if (rem > 2) rem = 2;
        if      (rem == 2) asm volatile("cp.async.wait_group 2;");
        else if (rem == 1) asm volatile("cp.async.wait_group 1;");
        else               asm volatile("cp.async.wait_group 0;");
        __syncthreads();

        const __nv_bfloat16* Ah = sm + (size_t)(t % 3) * STAGE_E;
        const __nv_bfloat16* Al = Ah + AH_E;
        const __nv_bfloat16* Bh = Al + AH_E;
        const __nv_bfloat16* Bl = Bh + BH_E;

        #pragma unroll
        for (int kf = 0; kf < 2; kf++) {
            const int kb = kf*16 + 2*tig;
            uint32_t ah[MFRAG][4], al[MFRAG][4];
            #pragma unroll
            for (int mi = 0; mi < MFRAG; mi++) {
                int r0 = m_warp + mi*16 + gid;
                ah[mi][0] = *(const uint32_t*)&Ah[r0*SSTH + kb];
                ah[mi][1] = *(const uint32_t*)&Ah[(r0+8)*SSTH + kb];
                ah[mi][2] = *(const uint32_t*)&Ah[r0*SSTH + kb + 8];
                ah[mi][3] = *(const uint32_t*)&Ah[(r0+8)*SSTH + kb + 8];
                al[mi][0] = *(const uint32_t*)&Al[r0*SSTH + kb];
                al[mi][1] = *(const uint32_t*)&Al[(r0+8)*SSTH + kb];
                al[mi][2] = *(const uint32_t*)&Al[r0*SSTH + kb + 8];
                al[mi][3] = *(const uint32_t*)&Al[(r0+8)*SSTH + kb + 8];
            }
            uint32_t bh[NFRAG][2], bl[NFRAG][2];
            #pragma unroll
            for (int ni = 0; ni < NFRAG; ni++) {
                int c0 = n_warp + ni*8 + gid;
                bh[ni][0] = *(const uint32_t*)&Bh[c0*SSTH + kb];
                bh[ni][1] = *(const uint32_t*)&Bh[c0*SSTH + kb + 8];
                bl[ni][0] = *(const uint32_t*)&Bl[c0*SSTH + kb];
                bl[ni][1] = *(const uint32_t*)&Bl[c0*SSTH + kb + 8];
            }
            // pass-major ordering: consecutive HMMAs hit distinct accumulators
            #pragma unroll
            for (int mi = 0; mi < MFRAG; mi++)
                #pragma unroll
                for (int ni = 0; ni < NFRAG; ni++) mma16(acc[mi][ni], ah[mi], bh[ni]);
            #pragma unroll
            for (int mi = 0; mi < MFRAG; mi++)
                #pragma unroll
                for (int ni = 0; ni < NFRAG; ni++) mma16(acc[mi][ni], ah[mi], bl[ni]);
            #pragma unroll
            for (int mi = 0; mi < MFRAG; mi++)
                #pragma unroll
                for (int ni = 0; ni < NFRAG; ni++) mma16(acc[mi][ni], al[mi], bh[ni]);
        }
        __syncthreads();
    }

    // ---------------- epilogue ----------------
    #pragma unroll
    for (int mi = 0; mi < MFRAG; mi++) {
        #pragma unroll
        for (int ni = 0; ni < NFRAG; ni++) {
            int col = bn + n_warp + ni*8 + tig*2;
            float* a4 = acc[mi][ni];
            #pragma unroll
            for (int half = 0; half < 2; half++) {
                int r = bm + m_warp + mi*16 + gid + half*8;
                if (r >= M) continue;
                float v0 = a4[half*2];
                float v1 = a4[half*2+1];
                if (MODE == 0) {
                    v0 += __ldg(bias + col); v1 += __ldg(bias + col + 1);
                    *(float2*)&C[(size_t)r*N + col] = make_float2(v0, v1);
                } else if (MODE == 1) {
                    v0 = gelu_exact(v0 + __ldg(bias + col));
                    v1 = gelu_exact(v1 + __ldg(bias + col + 1));
                    __nv_bfloat16 h0, l0, h1, l1;
                    bsplit(v0, h0, l0); bsplit(v1, h1, l1);
                    *(__nv_bfloat162*)&Chi[(size_t)r*N + col] = __nv_bfloat162(h0, h1);
                    *(__nv_bfloat162*)&Clo[(size_t)r*N + col] = __nv_bfloat162(l0, l1);
                } else {  // MODE 2
                    if (col < 256) {
                        v0 += __ldg(bias + col); v1 += __ldg(bias + col + 1);
                        *(float2*)&C[(size_t)r*MM + col] = make_float2(v0, v1);
                    } else {
                        v0 += __ldg(bias2 + col - 256); v1 += __ldg(bias2 + col - 255);
                        *(float2*)&C2[(size_t)r*MM + col - 256] = make_float2(v0, v1);
                    }
                }
            }
        }
    }
}

// ---------------- attention ----------------
__global__ void attn_kernel(const float* __restrict__ qkv) {
    int b = blockIdx.x, h = blockIdx.y;
    __shared__ float sk[NP1 * (DH + 1)];
    __shared__ float ss[NP1 * 66];
    int tid = threadIdx.x;
    int warp = tid >> 5, lane = tid & 31;

    for (int idx = tid; idx < NP1*DH; idx += 256) {
        int t = idx >> 6, d = idx & 63;
        size_t base = (size_t)(b*NP1 + t) * (3*DD) + h*DH + d;
        sk[t*(DH+1) + d] = qkv[base + DD];
    }
    __syncthreads();

    const float scale = 0.125f;
    for (int idx = tid; idx < NP1*NP1; idx += 256) {
        int r = idx / NP1, c = idx - r*NP1;
        const float* qp = qkv + (size_t)(b*NP1 + r) * (3*DD) + h*DH;
        const float* kk = sk + c*(DH+1);
        float s = 0.0f;
        #pragma unroll 16
        for (int d = 0; d < DH; d++) s = fmaf(__ldg(qp + d), kk[d], s);
        ss[r*66 + c] = s * scale;
    }
    __syncthreads();

    for (int r = warp; r < NP1; r += 8) {
        float* rowp = ss + r*66;
        float m = -1e30f;
        for (int c = lane; c < NP1; c += 32) m = fmaxf(m, rowp[c]);
        #pragma unroll
        for (int o = 16; o > 0; o >>= 1) m = fmaxf(m, __shfl_xor_sync(0xffffffffu, m, o));
        float s = 0.0f;
        for (int c = lane; c < NP1; c += 32) { float e = __expf(rowp[c] - m); rowp[c] = e; s += e; }
        #pragma unroll
        for (int o = 16; o > 0; o >>= 1) s += __shfl_xor_sync(0xffffffffu, s, o);
        float inv = 1.0f / s;
        for (int c = lane; c < NP1; c += 32) rowp[c] *= inv;
    }
    __syncthreads();

    for (int idx = tid; idx < NP1*DH; idx += 256) {
        int r = idx >> 6, d = idx & 63;
        const float* rowp = ss + r*66;
        float o = 0.0f;
        #pragma unroll 5
        for (int t = 0; t < NP1; t++) {
            const float* v = qkv + (size_t)(b*NP1 + t) * (3*DD) + 2*DD + h*DH + d;
            o = fmaf(rowp[t], __ldg(v), o);
        }
        size_t gi = (size_t)(b*NP1 + r)*DD + h*DH + d;
        __nv_bfloat16 hh, ll;
        bsplit(o, hh, ll);
        g_athi[gi] = hh; g_atlo[gi] = ll;
    }
}

// ---------------- residual add + layernorm ----------------
__global__ void resid_ln_kernel(float* __restrict__ xs,
                                const float* __restrict__ add,
                                const float* __restrict__ g,
                                const float* __restrict__ bb) {
    int t = blockIdx.x, tid = threadIdx.x;
    __shared__ float red[8];
    size_t base = (size_t)t * DD;
    float v0 = xs[base + tid]       + add[base + tid];
    float v1 = xs[base + tid + 256] + add[base + tid + 256];
    float s  = blockSum256(v0 + v1, red);
    float mu = s * (1.0f/512.0f);
    float d0 = v0 - mu, d1 = v1 - mu;
    float vs = blockSum256(d0*d0 + d1*d1, red);
    float inv = rsqrtf(vs * (1.0f/512.0f) + 1e-5f);
    float z0 = d0*inv*g[tid]       + bb[tid];
    float z1 = d1*inv*g[tid + 256] + bb[tid + 256];
    xs[base + tid]       = z0;
    xs[base + tid + 256] = z1;
    __nv_bfloat16 h, l;
    bsplit(z0, h, l); g_xshi[base + tid] = h;       g_xslo[base + tid] = l;
    bsplit(z1, h, l); g_xshi[base + tid + 256] = h; g_xslo[base + tid + 256] = l;
}

// ---------------- final drift / correction -> h_pot ----------------
__global__ void hpot_kernel(const float* __restrict__ marg,
                            const float* __restrict__ xg,
                            float* __restrict__ out) {
    int b = blockIdx.x, n = blockIdx.y;
    int i = threadIdx.x;
    __shared__ float red[8];

    float x0   = __ldg(xg);
    float xend = __ldg(xg + 255);
    float delta = (xend - x0) * (1.0f/255.0f);
    float xi = __ldg(xg + i);

    float hr = g_hraw[(size_t)(b*NP1 + n)*MM + i];
    float u  = hr * 100.0f * delta;
    float Mv;
    if (fabsf(u) < 1e-3f) {
        Mv = 127.5f - u*5461.25f + u*u*u*5965232.4f;
    } else {
        Mv = 1.0f/expm1f(u) - 256.0f/expm1f(256.0f*u);
    }
    float drift = (x0 + delta*Mv) - xi;

    float mu = marg[(size_t)(b*NP1 + n)*MM + i];
    float wd = blockSum256(mu * drift, red);
    float wm = blockSum256(mu, red);
    float corr = wd / (wm + 1e-8f);
    out[U_SIZE + (size_t)(b*64 + n)*MM + i] = hr - corr;
}

// ---------------- launch ----------------
extern "C" void kernel_launch(void* const* d_in, const int* in_sizes, int n_in,
                              void* d_out, int out_size) {
    const float* marg   = (const float*)d_in[0];
    const float* xg     = (const float*)d_in[1];
    const float* conv_w = (const float*)d_in[2];
    const float* conv_b = (const float*)d_in[3];
    const float* fc_w   = (const float*)d_in[4];
    const float* fc_b   = (const float*)d_in[5];
    const float* ln0_g  = (const float*)d_in[6];
    const float* ln0_b  = (const float*)d_in[7];
    const float* pos    = (const float*)d_in[8];
    const float* qkv_w  = (const float*)d_in[9];
    const float* qkv_b  = (const float*)d_in[10];
    const float* out_w  = (const float*)d_in[11];
    const float* out_b  = (const float*)d_in[12];
    const float* ln1_g  = (const float*)d_in[13];
    const float* ln1_b  = (const float*)d_in[14];
    const float* ff1_w  = (const float*)d_in[15];
    const float* ff1_b  = (const float*)d_in[16];
    const float* ff2_w  = (const float*)d_in[17];
    const float* ff2_b  = (const float*)d_in[18];
    const float* ln2_g  = (const float*)d_in[19];
    const float* ln2_b  = (const float*)d_in[20];
    const float* u_w    = (const float*)d_in[21];
    const float* u_b    = (const float*)d_in[22];
    const float* h_w    = (const float*)d_in[23];
    const float* h_b    = (const float*)d_in[24];
    float* out = (float*)d_out;

    float *xs, *buf, *hraw;
    __nv_bfloat16 *xshi, *xslo, *athi, *atlo, *ffhi, *fflo, *whi, *wlo;
    cudaGetSymbolAddress((void**)&xs,   g_xs);
    cudaGetSymbolAddress((void**)&buf,  g_buf);
    cudaGetSymbolAddress((void**)&hraw, g_hraw);
    cudaGetSymbolAddress((void**)&xshi, g_xshi);
    cudaGetSymbolAddress((void**)&xslo, g_xslo);
    cudaGetSymbolAddress((void**)&athi, g_athi);
    cudaGetSymbolAddress((void**)&atlo, g_atlo);
    cudaGetSymbolAddress((void**)&ffhi, g_ffhi);
    cudaGetSymbolAddress((void**)&fflo, g_fflo);
    cudaGetSymbolAddress((void**)&whi,  g_whi);
    cudaGetSymbolAddress((void**)&wlo,  g_wlo);

    // smem: 3 stages * (2*128*40 + 2*BN*40) halves * 2B
    const int SM64 = 3 * (2*128*SSTH + 2*64*SSTH) * 2;   // 92160
    const int SM32 = 3 * (2*128*SSTH + 2*32*SSTH) * 2;   // 76800
    static bool attr_done = false;
    if (!attr_done) {
        cudaFuncSetAttribute(gemm_bf16<64,0>, cudaFuncAttributeMaxDynamicSharedMemorySize, SM64);
        cudaFuncSetAttribute(gemm_bf16<64,1>, cudaFuncAttributeMaxDynamicSharedMemorySize, SM64);
        cudaFuncSetAttribute(gemm_bf16<32,0>, cudaFuncAttributeMaxDynamicSharedMemorySize, SM32);
        cudaFuncSetAttribute(gemm_bf16<32,2>, cudaFuncAttributeMaxDynamicSharedMemorySize, SM32);
        attr_done = true;
    }

    const int MT = (NT + 127) / 128;   // 9

    split_all<<<4096, 256>>>((const float4*)qkv_w, (const float4*)out_w,
                             (const float4*)ff1_w, (const float4*)ff2_w,
                             (const float4*)u_w,   (const float4*)h_w);

    embed_kernel<<<NT, 256>>>(marg, conv_w, conv_b, fc_w, fc_b, ln0_g, ln0_b, pos);

    for (int l = 0; l < LL; l++) {
        gemm_bf16<64,0><<<dim3((3*DD)/64, MT), 256, SM64>>>(
            xshi, xslo, whi + OFF_QKV + (size_t)l*3*DD*DD, wlo + OFF_QKV + (size_t)l*3*DD*DD,
            qkv_b + (size_t)l*3*DD, nullptr, buf, nullptr, nullptr, nullptr, NT, 3*DD, DD);
        attn_kernel<<<dim3(BB, NH), 256>>>(buf);
        gemm_bf16<32,0><<<dim3(DD/32, MT), 256, SM32>>>(
            athi, atlo, whi + OFF_OUT + (size_t)l*DD*DD, wlo + OFF_OUT + (size_t)l*DD*DD,
            out_b + (size_t)l*DD, nullptr, buf, nullptr, nullptr, nullptr, NT, DD, DD);
        resid_ln_kernel<<<NT, 256>>>(xs, buf, ln1_g + (size_t)l*DD, ln1_b + (size_t)l*DD);
        gemm_bf16<64,1><<<dim3(DFFN/64, MT), 256, SM64>>>(
            xshi, xslo, whi + OFF_FF1 + (size_t)l*DFFN*DD, wlo + OFF_FF1 + (size_t)l*DFFN*DD,
            ff1_b + (size_t)l*DFFN, nullptr, nullptr, ffhi, fflo, nullptr, NT, DFFN, DD);
        gemm_bf16<32,0><<<dim3(DD/32, MT), 256, SM32>>>(
            ffhi, fflo, whi + OFF_FF2 + (size_t)l*DD*DFFN, wlo + OFF_FF2 + (size_t)l*DD*DFFN,
            ff2_b + (size_t)l*DD, nullptr, buf, nullptr, nullptr, nullptr, NT, DD, DFFN);
        resid_ln_kernel<<<NT, 256>>>(xs, buf, ln2_g + (size_t)l*DD, ln2_b + (size_t)l*DD);
    }

    // combined heads: rows 0..255 = u_w, 256..511 = h_w (adjacent in split buffer)
    gemm_bf16<32,2><<<dim3((2*MM)/32, MT), 256, SM32>>>(
        xshi, xslo, whi + OFF_U, wlo + OFF_U, u_b, h_b,
        out, nullptr, nullptr, hraw, NT, 2*MM, DD);

    hpot_kernel<<<dim3(BB, 64), 256>>>(marg, xg, out);
}